// round 16
// baseline (speedup 1.0000x reference)
#include <cuda_runtime.h>
#include <math.h>

#define Bb   4
#define Tdim 2048
#define Cdim 2048
#define BT   8192        // Bb*Tdim
#define H    16
#define HD   128
#define Rr   128
#define NB   16
#define BS   128
#define NBH  64          // Bb*H
#define KSPLIT 4

static const float SCALE_ATT = 0.08838834764831845f; // 1/sqrt(128)
#define FULLM 0xffffffffu

#define WSZ ((size_t)4 * Rr * Cdim)   // = 1,048,576 floats; lw == rw == diag size

// scratch (device globals: no allocation allowed)
__device__ float g_wr[(size_t)3 * WSZ];                 // [lw | rw | diag] rna-rounded
__device__ float g_tpart[(size_t)KSPLIT * BT * Rr];     // split-K partials (final proj)
__device__ float g_t[(size_t)3 * BT * Rr];
__device__ float g_qkv[(size_t)3 * Bb * Tdim * Cdim];
__device__ float g_y[(size_t)Bb * Tdim * Cdim];

// ---------------------------------------------------------------------------
// helpers
// ---------------------------------------------------------------------------
__device__ __forceinline__ unsigned f2tf32(float f) {
    unsigned r;
    asm("cvt.rna.tf32.f32 %0, %1;" : "=r"(r) : "f"(f));
    return r;
}
__device__ __forceinline__ float rnd(float f) { return __uint_as_float(f2tf32(f)); }

__device__ __forceinline__ void cp_async16(void* smem, const void* gmem) {
    unsigned s = (unsigned)__cvta_generic_to_shared(smem);
    asm volatile("cp.async.cg.shared.global [%0], [%1], 16;\n" :: "r"(s), "l"(gmem));
}
#define CP_COMMIT() asm volatile("cp.async.commit_group;\n" ::: "memory")
#define CP_WAIT0()  asm volatile("cp.async.wait_group 0;\n" ::: "memory")
#define CP_WAIT1()  asm volatile("cp.async.wait_group 1;\n" ::: "memory")

__device__ __forceinline__ void mma_tf32(float* c, const unsigned* a, const unsigned* b) {
    asm volatile(
        "mma.sync.aligned.m16n8k8.row.col.f32.tf32.tf32.f32 "
        "{%0,%1,%2,%3}, {%4,%5,%6,%7}, {%8,%9}, {%0,%1,%2,%3};\n"
        : "+f"(c[0]), "+f"(c[1]), "+f"(c[2]), "+f"(c[3])
        : "r"(a[0]), "r"(a[1]), "r"(a[2]), "r"(a[3]), "r"(b[0]), "r"(b[1]));
}
__device__ __forceinline__ unsigned ldu(const float* p) { return __float_as_uint(*p); }
// A-frag load: LDS + rna-cvt (x is raw fp32; t/y already rounded -> idempotent)
__device__ __forceinline__ unsigned lda(const float* p) { return f2tf32(*p); }

// ---------------------------------------------------------------------------
// K0: merged weight rounding: [lw | rw | diag] -> g_wr (each WSZ floats)
// ---------------------------------------------------------------------------
__global__ void round_w_kernel(const float* __restrict__ lw,
                               const float* __restrict__ rw,
                               const float* __restrict__ dg,
                               float* __restrict__ dst) {
    const size_t seg4 = WSZ / 4;
    size_t i = (size_t)blockIdx.x * blockDim.x + threadIdx.x;
    size_t stride = (size_t)gridDim.x * blockDim.x;
    for (; i < 3 * seg4; i += stride) {
        const float* src = (i < seg4) ? lw : (i < 2 * seg4 ? rw : dg);
        size_t off = i - (i < seg4 ? 0 : (i < 2 * seg4 ? seg4 : 2 * seg4));
        float4 v = ((const float4*)src)[off];
        v.x = rnd(v.x); v.y = rnd(v.y); v.z = rnd(v.z); v.w = rnd(v.w);
        ((float4*)dst)[i] = v;
    }
}

// reduce split-K partials + round
__global__ void reduce_t_kernel(const float* __restrict__ tpart,
                                float* __restrict__ t, size_t ps4, size_t n4) {
    size_t i = (size_t)blockIdx.x * blockDim.x + threadIdx.x;
    size_t stride = (size_t)gridDim.x * blockDim.x;
    for (; i < n4; i += stride) {
        float4 s = ((const float4*)tpart)[i];
#pragma unroll
        for (int z = 1; z < KSPLIT; z++) {
            float4 v = ((const float4*)tpart)[z * ps4 + i];
            s.x += v.x; s.y += v.y; s.z += v.z; s.w += v.w;
        }
        s.x = rnd(s.x); s.y = rnd(s.y); s.z = rnd(s.z); s.w = rnd(s.w);
        ((float4*)t)[i] = s;
    }
}

// ---------------------------------------------------------------------------
// smem layouts: nk rows LD 36 (frag addr 4g+tg distinct banks),
//               kn rows LD 136 (frag addr 8tg+g distinct banks)
// B stage must hold max(32x136, 128x36) = 4608 floats.
// ---------------------------------------------------------------------------
#define GS   4608
#define KNLD 136
#define AGS  9216
#define BGS  4608

__device__ __forceinline__ void cpa_128x32(float* S, const float* A, int ld, int tid) {
#pragma unroll
    for (int p = 0; p < 4; p++) {
        int idx = tid + p * 256;
        int row = idx >> 3, c4 = (idx & 7) << 2;
        cp_async16(S + row * 36 + c4, A + (size_t)row * ld + c4);
    }
}
__device__ __forceinline__ void cpa_256x32(float* S, const float* A, int ld, int tid) {
#pragma unroll
    for (int p = 0; p < 8; p++) {
        int idx = tid + p * 256;
        int row = idx >> 3, c4 = (idx & 7) << 2;
        cp_async16(S + row * 36 + c4, A + (size_t)row * ld + c4);
    }
}
__device__ __forceinline__ void cpa_32x128(float* S, const float* B, int ld, int tid) {
#pragma unroll
    for (int p = 0; p < 4; p++) {
        int idx = tid + p * 256;
        int kr = idx >> 5, n4 = (idx & 31) << 2;
        cp_async16(S + kr * KNLD + n4, B + (size_t)kr * ld + n4);
    }
}

// ---- 128x128 block (8 warps: wm 0..1, wn 0..3; warp 64x32) for left_proj ----
__device__ __forceinline__ void mma_step_nk(const float* As, const float* Bs,
                                            int wm, int wn, int lane, float acc[4][4][4]) {
    int g = lane >> 2, tg = lane & 3;
#pragma unroll
    for (int kk = 0; kk < 4; kk++) {
        int k = kk * 8;
        unsigned a[4][4], b[4][2];
#pragma unroll
        for (int im = 0; im < 4; im++) {
            const float* r0 = As + (wm * 64 + im * 16 + g) * 36;
            a[im][0] = lda(r0 + k + tg);
            a[im][1] = lda(r0 + 8 * 36 + k + tg);
            a[im][2] = lda(r0 + k + tg + 4);
            a[im][3] = lda(r0 + 8 * 36 + k + tg + 4);
        }
#pragma unroll
        for (int jn = 0; jn < 4; jn++) {
            const float* rn = Bs + (wn * 32 + jn * 8 + g) * 36;
            b[jn][0] = ldu(rn + k + tg);
            b[jn][1] = ldu(rn + k + tg + 4);
        }
#pragma unroll
        for (int im = 0; im < 4; im++)
#pragma unroll
            for (int jn = 0; jn < 4; jn++) mma_tf32(acc[im][jn], a[im], b[jn]);
    }
}

// ---- 256x128 block (8 warps: wm 0..3, wn 0..1; warp 64x64) for fused_out ----
__device__ __forceinline__ void mma_step_kn2(const float* As, const float* Bs,
                                             int wm, int wn, int lane, float acc[4][8][4]) {
    int g = lane >> 2, tg = lane & 3;
#pragma unroll
    for (int kk = 0; kk < 4; kk++) {
        int k = kk * 8;
        unsigned a[4][4], b[8][2];
#pragma unroll
        for (int im = 0; im < 4; im++) {
            const float* r0 = As + (wm * 64 + im * 16 + g) * 36;
            a[im][0] = lda(r0 + k + tg);
            a[im][1] = lda(r0 + 8 * 36 + k + tg);
            a[im][2] = lda(r0 + k + tg + 4);
            a[im][3] = lda(r0 + 8 * 36 + k + tg + 4);
        }
#pragma unroll
        for (int jn = 0; jn < 8; jn++) {
            int nb = wn * 64 + jn * 8 + g;
            b[jn][0] = ldu(Bs + (k + tg) * KNLD + nb);
            b[jn][1] = ldu(Bs + (k + tg + 4) * KNLD + nb);
        }
#pragma unroll
        for (int im = 0; im < 4; im++)
#pragma unroll
            for (int jn = 0; jn < 8; jn++) mma_tf32(acc[im][jn], a[im], b[jn]);
    }
}
__device__ __forceinline__ void mma_step_nk2(const float* As, const float* Bs,
                                             int wm, int wn, int lane, float acc[4][8][4]) {
    int g = lane >> 2, tg = lane & 3;
#pragma unroll
    for (int kk = 0; kk < 4; kk++) {
        int k = kk * 8;
        unsigned a[4][4], b[8][2];
#pragma unroll
        for (int im = 0; im < 4; im++) {
            const float* r0 = As + (wm * 64 + im * 16 + g) * 36;
            a[im][0] = lda(r0 + k + tg);
            a[im][1] = lda(r0 + 8 * 36 + k + tg);
            a[im][2] = lda(r0 + k + tg + 4);
            a[im][3] = lda(r0 + 8 * 36 + k + tg + 4);
        }
#pragma unroll
        for (int jn = 0; jn < 8; jn++) {
            const float* rn = Bs + (wn * 64 + jn * 8 + g) * 36;
            b[jn][0] = ldu(rn + k + tg);
            b[jn][1] = ldu(rn + k + tg + 4);
        }
#pragma unroll
        for (int im = 0; im < 4; im++)
#pragma unroll
            for (int jn = 0; jn < 8; jn++) mma_tf32(acc[im][jn], a[im], b[jn]);
    }
}

#define GEMM_SMEM  (4 * GS * 4)                 // 73728 B
#define GEMM2_SMEM ((2 * AGS + 2 * BGS) * 4)    // 110592 B

// ---------------------------------------------------------------------------
// K1a: direct left proj (qkv): t_y = rna(X @ L_y^T). grid (BT/128, 3).
// ---------------------------------------------------------------------------
__global__ __launch_bounds__(256, 2) void left_proj_direct(
    const float* __restrict__ X, const float* __restrict__ L, size_t Lstride,
    float* __restrict__ Tout, size_t Tstride) {
    extern __shared__ float gsm[];
    float* Aab = gsm;
    float* Bab = gsm + 2 * GS;
    int tid = threadIdx.x, lane = tid & 31, w = tid >> 5, wm = w >> 2, wn = w & 3;
    int m0 = blockIdx.x * 128;
    const float* Lp = L + blockIdx.y * Lstride;
    const float* Xp = X + (size_t)m0 * Cdim;
    float* Tp = Tout + blockIdx.y * Tstride;
    float acc[4][4][4] = {};

    cpa_128x32(Aab, Xp, Cdim, tid);
    cpa_128x32(Bab, Lp, Cdim, tid);
    CP_COMMIT();
    const int NS = Cdim / 32;
    for (int s = 0; s < NS; s++) {
        int st = s & 1;
        CP_WAIT0();
        __syncthreads();
        if (s + 1 < NS) {
            int nt = st ^ 1;
            cpa_128x32(Aab + nt * GS, Xp + (s + 1) * 32, Cdim, tid);
            cpa_128x32(Bab + nt * GS, Lp + (s + 1) * 32, Cdim, tid);
            CP_COMMIT();
        }
        mma_step_nk(Aab + st * GS, Bab + st * GS, wm, wn, lane, acc);
        __syncthreads();
    }
    int g = lane >> 2, tg = lane & 3;
#pragma unroll
    for (int im = 0; im < 4; im++)
#pragma unroll
        for (int jn = 0; jn < 4; jn++) {
            int r = m0 + wm * 64 + im * 16 + g;
            int c = wn * 32 + jn * 8 + tg * 2;
            Tp[(size_t)r * Rr + c]           = rnd(acc[im][jn][0]);
            Tp[(size_t)r * Rr + c + 1]       = rnd(acc[im][jn][1]);
            Tp[(size_t)(r + 8) * Rr + c]     = rnd(acc[im][jn][2]);
            Tp[(size_t)(r + 8) * Rr + c + 1] = rnd(acc[im][jn][3]);
        }
}

// ---------------------------------------------------------------------------
// K1b: split-K left proj (final only): tpart[z] = Y @ L3^T over K chunk z.
// grid (BT/128, 1, KSPLIT).
// ---------------------------------------------------------------------------
__global__ __launch_bounds__(256, 2) void left_proj_split(
    const float* __restrict__ X, const float* __restrict__ L,
    float* __restrict__ Tpart) {
    extern __shared__ float gsm[];
    float* Aab = gsm;
    float* Bab = gsm + 2 * GS;
    int tid = threadIdx.x, lane = tid & 31, w = tid >> 5, wm = w >> 2, wn = w & 3;
    int m0 = blockIdx.x * 128;
    int kz = blockIdx.z * (Cdim / KSPLIT);
    const float* Lp = L + kz;
    const float* Xp = X + (size_t)m0 * Cdim + kz;
    float* Tp = Tpart + (size_t)blockIdx.z * ((size_t)BT * Rr);
    float acc[4][4][4] = {};

    cpa_128x32(Aab, Xp, Cdim, tid);
    cpa_128x32(Bab, Lp, Cdim, tid);
    CP_COMMIT();
    const int NS = Cdim / KSPLIT / 32;  // 16
    for (int s = 0; s < NS; s++) {
        int st = s & 1;
        CP_WAIT0();
        __syncthreads();
        if (s + 1 < NS) {
            int nt = st ^ 1;
            cpa_128x32(Aab + nt * GS, Xp + (s + 1) * 32, Cdim, tid);
            cpa_128x32(Bab + nt * GS, Lp + (s + 1) * 32, Cdim, tid);
            CP_COMMIT();
        }
        mma_step_nk(Aab + st * GS, Bab + st * GS, wm, wn, lane, acc);
        __syncthreads();
    }
    int g = lane >> 2, tg = lane & 3;
#pragma unroll
    for (int im = 0; im < 4; im++)
#pragma unroll
        for (int jn = 0; jn < 4; jn++) {
            int r = m0 + wm * 64 + im * 16 + g;
            int c = wn * 32 + jn * 8 + tg * 2;
            Tp[(size_t)r * Rr + c]           = acc[im][jn][0];
            Tp[(size_t)r * Rr + c + 1]       = acc[im][jn][1];
            Tp[(size_t)(r + 8) * Rr + c]     = acc[im][jn][2];
            Tp[(size_t)(r + 8) * Rr + c + 1] = acc[im][jn][3];
        }
}

// ---------------------------------------------------------------------------
// K2: fused LORI output, 256x128 block tile. grid (BT/256, NB, nProj).
// ---------------------------------------------------------------------------
__global__ __launch_bounds__(256, 1) void fused_out_mma(
    const float* __restrict__ X,
    const float* __restrict__ Tl, size_t Tstride,
    const float* __restrict__ Dg, size_t Dstride,
    const float* __restrict__ RW, size_t RWstride,
    const float* __restrict__ rb,
    const float* __restrict__ bp, size_t Bstride,
    float* __restrict__ Y, size_t Ystride, int round_out) {
    extern __shared__ float gsm[];
    float* Aab = gsm;
    float* Bab = gsm + 2 * AGS;
    int tid = threadIdx.x, lane = tid & 31, w = tid >> 5, wm = w >> 1, wn = w & 1;
    int m0 = blockIdx.x * 256;
    int c0 = blockIdx.y * BS;
    int z = blockIdx.z;
    const float* Tlp = Tl + z * Tstride;
    const float* D   = Dg + z * Dstride + (size_t)blockIdx.y * BS * BS;
    const float* RWp = RW + z * RWstride;
    const float* rbp = rb + z * Bstride;
    const float* bpp = bp + z * Bstride;
    float* Yp        = Y  + z * Ystride;
    float acc[4][8][4] = {};

    cpa_256x32(Aab, X + (size_t)m0 * Cdim + c0, Cdim, tid);
    cpa_32x128(Bab, D, BS, tid);
    CP_COMMIT();
    for (int s = 0; s < 8; s++) {
        int st = s & 1;
        CP_WAIT0();
        __syncthreads();
        if (s + 1 < 8) {
            int nt = st ^ 1, s1 = s + 1;
            if (s1 < 4) {
                cpa_256x32(Aab + nt * AGS, X + (size_t)m0 * Cdim + c0 + s1 * 32, Cdim, tid);
                cpa_32x128(Bab + nt * BGS, D + (size_t)(s1 * 32) * BS, BS, tid);
            } else {
                cpa_256x32(Aab + nt * AGS, Tlp + (size_t)m0 * Rr + (s1 - 4) * 32, Rr, tid);
                cpa_128x32(Bab + nt * BGS, RWp + (size_t)c0 * Rr + (s1 - 4) * 32, Rr, tid);
            }
            CP_COMMIT();
        }
        if (s < 4) mma_step_kn2(Aab + st * AGS, Bab + st * BGS, wm, wn, lane, acc);
        else       mma_step_nk2(Aab + st * AGS, Bab + st * BGS, wm, wn, lane, acc);
        __syncthreads();
    }

    int g = lane >> 2, tg = lane & 3;
#pragma unroll
    for (int im = 0; im < 4; im++)
#pragma unroll
        for (int jn = 0; jn < 8; jn++) {
            int r = m0 + wm * 64 + im * 16 + g;
            int c = c0 + wn * 64 + jn * 8 + tg * 2;
            float b0 = rbp[c] + bpp[c], b1 = rbp[c + 1] + bpp[c + 1];
            float o00 = acc[im][jn][0] + b0, o01 = acc[im][jn][1] + b1;
            float o10 = acc[im][jn][2] + b0, o11 = acc[im][jn][3] + b1;
            if (round_out) { o00 = rnd(o00); o01 = rnd(o01); o10 = rnd(o10); o11 = rnd(o11); }
            Yp[(size_t)r * Cdim + c]           = o00;
            Yp[(size_t)r * Cdim + c + 1]       = o01;
            Yp[(size_t)(r + 8) * Cdim + c]     = o10;
            Yp[(size_t)(r + 8) * Cdim + c + 1] = o11;
        }
}

// ---------------------------------------------------------------------------
// K3: fused flash attention. grid (qt=16, bh=64), 8 warps. Q/K/V tf32-exact.
// ---------------------------------------------------------------------------
#define QLD 132
#define KLD 132
#define VLD 136
#define FA_SMEM ((128 * QLD + 128 * KLD + 128 * VLD) * 4)

__global__ __launch_bounds__(256) void flash_attn(const float* __restrict__ Q,
                                                  const float* __restrict__ Kg,
                                                  const float* __restrict__ Vg,
                                                  float* __restrict__ Y) {
    extern __shared__ float fsm[];
    float* Qs = fsm;
    float* Ks = fsm + 128 * QLD;
    float* Vs = fsm + 128 * QLD + 128 * KLD;

    int qt = gridDim.x - 1 - blockIdx.x;
    int bh = blockIdx.y;
    int b = bh / H, h = bh % H;
    const float* Qp = Q  + (size_t)b * Tdim * Cdim + (size_t)h * HD;
    const float* Kp = Kg + (size_t)b * Tdim * Cdim + (size_t)h * HD;
    const float* Vp = Vg + (size_t)b * Tdim * Cdim + (size_t)h * HD;
    float* Yp       = Y  + (size_t)b * Tdim * Cdim + (size_t)h * HD;

    int tid = threadIdx.x, lane = tid & 31, w = tid >> 5;
    int g = lane >> 2, tg = lane & 3;
    int qr = w * 16;

#pragma unroll
    for (int p = 0; p < 16; p++) {
        int idx = tid + p * 256;
        int row = idx >> 5, c4 = (idx & 31) << 2;
        cp_async16(Qs + row * QLD + c4, Qp + (size_t)(qt * 128 + row) * Cdim + c4);
    }
#pragma unroll
    for (int p = 0; p < 16; p++) {
        int idx = tid + p * 256;
        int row = idx >> 5, c4 = (idx & 31) << 2;
        cp_async16(Ks + row * KLD + c4, Kp + (size_t)row * Cdim + c4);
    }
    CP_COMMIT();
#pragma unroll
    for (int p = 0; p < 16; p++) {
        int idx = tid + p * 256;
        int row = idx >> 5, c4 = (idx & 31) << 2;
        cp_async16(Vs + row * VLD + c4, Vp + (size_t)row * Cdim + c4);
    }
    CP_COMMIT();

    float acco[16][4] = {};
    float m0 = -1e30f, m1 = -1e30f;
    float l0 = 0.f, l1 = 0.f;

    for (int kt = 0; kt <= qt; kt++) {
        CP_WAIT1();
        __syncthreads();

        float accs[16][4] = {};
#pragma unroll
        for (int kk = 0; kk < 16; kk++) {
            int kg = kk * 8;
            unsigned aq[4];
            const float* q0 = Qs + (qr + g) * QLD;
            aq[0] = ldu(q0 + kg + tg);
            aq[1] = ldu(q0 + 8 * QLD + kg + tg);
            aq[2] = ldu(q0 + kg + tg + 4);
            aq[3] = ldu(q0 + 8 * QLD + kg + tg + 4);
#pragma unroll
            for (int nb = 0; nb < 16; nb++) {
                unsigned bb[2];
                const float* kr = Ks + (nb * 8 + g) * KLD;
                bb[0] = ldu(kr + kg + tg);
                bb[1] = ldu(kr + kg + tg + 4);
                mma_tf32(accs[nb], aq, bb);
            }
        }
        __syncthreads();
        if (kt < qt) {
#pragma unroll
            for (int p = 0; p < 16; p++) {
                int idx = tid + p * 256;
                int row = idx >> 5, c4 = (idx & 31) << 2;
                cp_async16(Ks + row * KLD + c4,
                           Kp + (size_t)((kt + 1) * 128 + row) * Cdim + c4);
            }
            CP_COMMIT();
        }

        bool diag = (kt == qt);
        int rl0 = qr + g, rl1 = qr + g + 8;
        float mx0 = -1e30f, mx1 = -1e30f;
#pragma unroll
        for (int nb = 0; nb < 16; nb++) {
            int cl = nb * 8 + 2 * tg;
            float v0 = accs[nb][0] * SCALE_ATT;
            float v1 = accs[nb][1] * SCALE_ATT;
            float v2 = accs[nb][2] * SCALE_ATT;
            float v3 = accs[nb][3] * SCALE_ATT;
            if (diag) {
                if (cl     > rl0) v0 = -1e30f;
                if (cl + 1 > rl0) v1 = -1e30f;
                if (cl     > rl1) v2 = -1e30f;
                if (cl + 1 > rl1) v3 = -1e30f;
            }
            accs[nb][0] = v0; accs[nb][1] = v1; accs[nb][2] = v2; accs[nb][3] = v3;
            mx0 = fmaxf(mx0, fmaxf(v0, v1));
            mx1 = fmaxf(mx1, fmaxf(v2, v3));
        }
        mx0 = fmaxf(mx0, __shfl_xor_sync(FULLM, mx0, 1));
        mx0 = fmaxf(mx0, __shfl_xor_sync(FULLM, mx0, 2));
        mx1 = fmaxf(mx1, __shfl_xor_sync(FULLM, mx1, 1));
        mx1 = fmaxf(mx1, __shfl_xor_sync(FULLM, mx1, 2));

        float mn0 = fmaxf(m0, mx0), mn1 = fmaxf(m1, mx1);
        float sc0 = __expf(m0 - mn0), sc1 = __expf(m1 - mn1);
        m0 = mn0; m1 = mn1;
        float s0 = 0.f, s1 = 0.f;
#pragma unroll
        for (int nb = 0; nb < 16; nb++) {
            float p0 = __expf(accs[nb][0] - mn0);
            float p1 = __expf(accs[nb][1] - mn0);
            float p2 = __expf(accs[nb][2] - mn1);
            float p3 = __expf(accs[nb][3] - mn1);
            s0 += p0 + p1; s1 += p2 + p3;
            accs[nb][0] = __uint_as_float(f2tf32(p0));
            accs[nb][1] = __uint_as_float(f2tf32(p1));
            accs[nb][2] = __uint_as_float(f2tf32(p2));
            accs[nb][3] = __uint_as_float(f2tf32(p3));
        }
        s0 += __shfl_xor_sync(FULLM, s0, 1);
        s0 += __shfl_xor_sync(FULLM, s0, 2);
        s1 += __shfl_xor_sync(FULLM, s1, 1);
        s1 += __shfl_xor_sync(FULLM, s1, 2);
        l0 = l0 * sc0 + s0; l1 = l1 * sc1 + s1;
#pragma unroll
        for (int nb = 0; nb < 16; nb++) {
            acco[nb][0] *= sc0; acco[nb][1] *= sc0;
            acco[nb][2] *= sc1; acco[nb][3] *= sc1;
        }

        if (kt < qt) CP_WAIT1(); else CP_WAIT0();   // last-iter edge case
        __syncthreads();

#pragma unroll
        for (int kb = 0; kb < 16; kb++) {
            float c0 = accs[kb][0], c1 = accs[kb][1];
            float c2 = accs[kb][2], c3 = accs[kb][3];
            int q0 = (lane & ~3) | (tg >> 1);
            int q1 = q0 | 2;
            bool odd = tg & 1;
            float t00 = __shfl_sync(FULLM, c0, q0), t01 = __shfl_sync(FULLM, c1, q0);
            float t10 = __shfl_sync(FULLM, c2, q0), t11 = __shfl_sync(FULLM, c3, q0);
            float t20 = __shfl_sync(FULLM, c0, q1), t21 = __shfl_sync(FULLM, c1, q1);
            float t30 = __shfl_sync(FULLM, c2, q1), t31 = __shfl_sync(FULLM, c3, q1);
            unsigned ap[4];
            ap[0] = __float_as_uint(odd ? t01 : t00);
            ap[1] = __float_as_uint(odd ? t11 : t10);
            ap[2] = __float_as_uint(odd ? t21 : t20);
            ap[3] = __float_as_uint(odd ? t31 : t30);
            int kg = kb * 8;
#pragma unroll
            for (int nb = 0; nb < 16; nb++) {
                unsigned bb[2];
                bb[0] = ldu(Vs + (kg + tg) * VLD + nb * 8 + g);
                bb[1] = ldu(Vs + (kg + tg + 4) * VLD + nb * 8 + g);
                mma_tf32(acco[nb], ap, bb);
            }
        }
        __syncthreads();
        if (kt < qt) {
#pragma unroll
            for (int p = 0; p < 16; p++) {
                int idx = tid + p * 256;
                int row = idx >> 5, c4 = (idx & 31) << 2;
                cp_async16(Vs + row * VLD + c4,
                           Vp + (size_t)((kt + 1) * 128 + row) * Cdim + c4);
            }
            CP_COMMIT();
        }
    }

    float inv0 = 1.0f / l0, inv1 = 1.0f / l1;
    int r0 = qt * 128 + qr + g, r1 = r0 + 8;
#pragma unroll
    for (int nb = 0; nb < 16; nb++) {
        int cc = nb * 8 + 2 * tg;
        float2 o0 = make_float2(rnd(acco[nb][0] * inv0), rnd(acco[nb][1] * inv0));
        float2 o1 = make_float2(rnd(acco[nb][2] * inv1), rnd(acco[nb][3] * inv1));
        *(float2*)(Yp + (size_t)r0 * Cdim + cc) = o0;
        *(float2*)(Yp + (size_t)r1 * Cdim + cc) = o1;
    }
}

// ---------------------------------------------------------------------------
extern "C" void kernel_launch(void* const* d_in, const int* in_sizes, int n_in,
                              void* d_out, int out_size) {
    const float* x    = (const float*)d_in[0];
    const float* diag = (const float*)d_in[1];
    const float* left = (const float*)d_in[2];
    const float* rw   = (const float*)d_in[3];
    const float* rb   = (const float*)d_in[4];
    const float* bp   = (const float*)d_in[5];
    float* out = (float*)d_out;

    float *pwr, *ptpart, *pt, *pqkv, *py;
    cudaGetSymbolAddress((void**)&pwr, g_wr);
    cudaGetSymbolAddress((void**)&ptpart, g_tpart);
    cudaGetSymbolAddress((void**)&pt, g_t);
    cudaGetSymbolAddress((void**)&pqkv, g_qkv);
    cudaGetSymbolAddress((void**)&py, g_y);

    static bool attr_done = false;
    if (!attr_done) {
        cudaFuncSetAttribute(flash_attn, cudaFuncAttributeMaxDynamicSharedMemorySize, FA_SMEM);
        cudaFuncSetAttribute(left_proj_direct, cudaFuncAttributeMaxDynamicSharedMemorySize, GEMM_SMEM);
        cudaFuncSetAttribute(left_proj_split, cudaFuncAttributeMaxDynamicSharedMemorySize, GEMM_SMEM);
        cudaFuncSetAttribute(fused_out_mma, cudaFuncAttributeMaxDynamicSharedMemorySize, GEMM2_SMEM);
        attr_done = true;
    }

    const size_t PC = (size_t)BT * Cdim;   // activation plane
    const size_t PT = (size_t)BT * Rr;     // t plane
    float* plw = pwr;                      // rounded left_w
    float* prw = pwr + WSZ;                // rounded right_w
    float* pdg = pwr + 2 * WSZ;            // rounded diag

    // 0. round weights (one merged kernel, 12 MB)
    round_w_kernel<<<512, 256>>>(left, rw, diag, pwr);

    // 1. q,k,v left proj (direct, rounded epilogue)
    left_proj_direct<<<dim3(BT / 128, 3), 256, GEMM_SMEM>>>(
        x, plw, (size_t)Rr * Cdim, pt, PT);

    // 2. q,k,v fused output (rounded for flash)
    fused_out_mma<<<dim3(BT / 256, NB, 3), 256, GEMM2_SMEM>>>(
        x, pt, PT,
        pdg, (size_t)NB * BS * BS,
        prw, (size_t)Cdim * Rr,
        rb, bp, (size_t)Cdim,
        pqkv, PC, 1);

    // 3. attention (y rounded in epilogue)
    flash_attn<<<dim3(16, NBH), 256, FA_SMEM>>>(pqkv, pqkv + PC, pqkv + 2 * PC, py);

    // 4. output projection: split-K left (64 -> 256 blocks) + reduce + fused
    left_proj_split<<<dim3(BT / 128, 1, KSPLIT), 256, GEMM_SMEM>>>(
        py, plw + (size_t)3 * Rr * Cdim, ptpart);
    reduce_t_kernel<<<1184, 256>>>(ptpart, pt, PT / 4, PT / 4);
    fused_out_mma<<<dim3(BT / 256, NB, 1), 256, GEMM2_SMEM>>>(
        py, pt, 0,
        pdg + (size_t)3 * NB * BS * BS, 0,
        prw + (size_t)3 * Cdim * Rr, 0,
        rb + (size_t)3 * Cdim, bp + (size_t)3 * Cdim, 0,
        out, PC, 0);
}

// round 17
// speedup vs baseline: 1.0642x; 1.0642x over previous
#include <cuda_runtime.h>
#include <math.h>

#define Bb   4
#define Tdim 2048
#define Cdim 2048
#define BT   8192        // Bb*Tdim
#define H    16
#define HD   128
#define Rr   128
#define NB   16
#define BS   128
#define NBH  64          // Bb*H
#define KSPLIT 4

static const float SCALE_ATT = 0.08838834764831845f; // 1/sqrt(128)
#define FULLM 0xffffffffu

#define WSZ ((size_t)4 * Rr * Cdim)   // lw == rw == diag element count

// scratch (device globals: no allocation allowed)
__device__ float g_xr[(size_t)BT * Cdim];               // x rna-rounded
__device__ float g_wr[(size_t)3 * WSZ];                 // [lw | rw | diag] rounded
__device__ float g_tpart[(size_t)KSPLIT * BT * Rr];     // split-K partials (final)
__device__ float g_t[(size_t)3 * BT * Rr];
__device__ float g_qkv[(size_t)3 * Bb * Tdim * Cdim];
__device__ float g_y[(size_t)Bb * Tdim * Cdim];

// ---------------------------------------------------------------------------
// helpers
// ---------------------------------------------------------------------------
__device__ __forceinline__ unsigned f2tf32(float f) {
    unsigned r;
    asm("cvt.rna.tf32.f32 %0, %1;" : "=r"(r) : "f"(f));
    return r;
}
__device__ __forceinline__ float rnd(float f) { return __uint_as_float(f2tf32(f)); }

__device__ __forceinline__ void cp_async16(void* smem, const void* gmem) {
    unsigned s = (unsigned)__cvta_generic_to_shared(smem);
    asm volatile("cp.async.cg.shared.global [%0], [%1], 16;\n" :: "r"(s), "l"(gmem));
}
#define CP_COMMIT() asm volatile("cp.async.commit_group;\n" ::: "memory")
#define CP_WAIT0()  asm volatile("cp.async.wait_group 0;\n" ::: "memory")
#define CP_WAIT1()  asm volatile("cp.async.wait_group 1;\n" ::: "memory")

__device__ __forceinline__ void mma_tf32(float* c, const unsigned* a, const unsigned* b) {
    asm volatile(
        "mma.sync.aligned.m16n8k8.row.col.f32.tf32.tf32.f32 "
        "{%0,%1,%2,%3}, {%4,%5,%6,%7}, {%8,%9}, {%0,%1,%2,%3};\n"
        : "+f"(c[0]), "+f"(c[1]), "+f"(c[2]), "+f"(c[3])
        : "r"(a[0]), "r"(a[1]), "r"(a[2]), "r"(a[3]), "r"(b[0]), "r"(b[1]));
}
__device__ __forceinline__ unsigned ldu(const float* p) { return __float_as_uint(*p); }

// ---------------------------------------------------------------------------
// K0a: round x. K0b: round weights [lw | rw | diag]
// ---------------------------------------------------------------------------
__global__ void round_x_kernel(const float* __restrict__ src,
                               float* __restrict__ dst, size_t n4) {
    size_t i = (size_t)blockIdx.x * blockDim.x + threadIdx.x;
    size_t stride = (size_t)gridDim.x * blockDim.x;
    for (; i < n4; i += stride) {
        float4 v = ((const float4*)src)[i];
        v.x = rnd(v.x); v.y = rnd(v.y); v.z = rnd(v.z); v.w = rnd(v.w);
        ((float4*)dst)[i] = v;
    }
}
__global__ void round_w_kernel(const float* __restrict__ lw,
                               const float* __restrict__ rw,
                               const float* __restrict__ dg,
                               float* __restrict__ dst) {
    const size_t seg4 = WSZ / 4;
    size_t i = (size_t)blockIdx.x * blockDim.x + threadIdx.x;
    size_t stride = (size_t)gridDim.x * blockDim.x;
    for (; i < 3 * seg4; i += stride) {
        const float* src = (i < seg4) ? lw : (i < 2 * seg4 ? rw : dg);
        size_t off = i - (i < seg4 ? 0 : (i < 2 * seg4 ? seg4 : 2 * seg4));
        float4 v = ((const float4*)src)[off];
        v.x = rnd(v.x); v.y = rnd(v.y); v.z = rnd(v.z); v.w = rnd(v.w);
        ((float4*)dst)[i] = v;
    }
}

// reduce split-K partials + round
__global__ void reduce_t_kernel(const float* __restrict__ tpart,
                                float* __restrict__ t, size_t ps4, size_t n4) {
    size_t i = (size_t)blockIdx.x * blockDim.x + threadIdx.x;
    size_t stride = (size_t)gridDim.x * blockDim.x;
    for (; i < n4; i += stride) {
        float4 s = ((const float4*)tpart)[i];
#pragma unroll
        for (int z = 1; z < KSPLIT; z++) {
            float4 v = ((const float4*)tpart)[z * ps4 + i];
            s.x += v.x; s.y += v.y; s.z += v.z; s.w += v.w;
        }
        s.x = rnd(s.x); s.y = rnd(s.y); s.z = rnd(s.z); s.w = rnd(s.w);
        ((float4*)t)[i] = s;
    }
}

// ---------------------------------------------------------------------------
// smem layouts: nk rows LD 36 (frag addr 4g+tg distinct banks),
//               kn rows LD 136 (frag addr 8tg+g distinct banks)
// Stage size GS=4608 holds both 128x36 (4608) and 32x136 (4352).
// ---------------------------------------------------------------------------
#define GS   4608
#define KNLD 136

__device__ __forceinline__ void cpa_128x32(float* S, const float* A, int ld, int tid) {
#pragma unroll
    for (int p = 0; p < 4; p++) {
        int idx = tid + p * 256;
        int row = idx >> 3, c4 = (idx & 7) << 2;
        cp_async16(S + row * 36 + c4, A + (size_t)row * ld + c4);
    }
}
__device__ __forceinline__ void cpa_32x128(float* S, const float* B, int ld, int tid) {
#pragma unroll
    for (int p = 0; p < 4; p++) {
        int idx = tid + p * 256;
        int kr = idx >> 5, n4 = (idx & 31) << 2;
        cp_async16(S + kr * KNLD + n4, B + (size_t)kr * ld + n4);
    }
}

// ---- 128x128 block (8 warps: wm 0..1, wn 0..3; warp 64x32) ----
__device__ __forceinline__ void mma_step_nk(const float* As, const float* Bs,
                                            int wm, int wn, int lane, float acc[4][4][4]) {
    int g = lane >> 2, tg = lane & 3;
#pragma unroll
    for (int kk = 0; kk < 4; kk++) {
        int k = kk * 8;
        unsigned a[4][4], b[4][2];
#pragma unroll
        for (int im = 0; im < 4; im++) {
            const float* r0 = As + (wm * 64 + im * 16 + g) * 36;
            a[im][0] = ldu(r0 + k + tg);
            a[im][1] = ldu(r0 + 8 * 36 + k + tg);
            a[im][2] = ldu(r0 + k + tg + 4);
            a[im][3] = ldu(r0 + 8 * 36 + k + tg + 4);
        }
#pragma unroll
        for (int jn = 0; jn < 4; jn++) {
            const float* rn = Bs + (wn * 32 + jn * 8 + g) * 36;
            b[jn][0] = ldu(rn + k + tg);
            b[jn][1] = ldu(rn + k + tg + 4);
        }
#pragma unroll
        for (int im = 0; im < 4; im++)
#pragma unroll
            for (int jn = 0; jn < 4; jn++) mma_tf32(acc[im][jn], a[im], b[jn]);
    }
}
__device__ __forceinline__ void mma_step_kn(const float* As, const float* Bs,
                                            int wm, int wn, int lane, float acc[4][4][4]) {
    int g = lane >> 2, tg = lane & 3;
#pragma unroll
    for (int kk = 0; kk < 4; kk++) {
        int k = kk * 8;
        unsigned a[4][4], b[4][2];
#pragma unroll
        for (int im = 0; im < 4; im++) {
            const float* r0 = As + (wm * 64 + im * 16 + g) * 36;
            a[im][0] = ldu(r0 + k + tg);
            a[im][1] = ldu(r0 + 8 * 36 + k + tg);
            a[im][2] = ldu(r0 + k + tg + 4);
            a[im][3] = ldu(r0 + 8 * 36 + k + tg + 4);
        }
#pragma unroll
        for (int jn = 0; jn < 4; jn++) {
            int nb = wn * 32 + jn * 8 + g;
            b[jn][0] = ldu(Bs + (k + tg) * KNLD + nb);
            b[jn][1] = ldu(Bs + (k + tg + 4) * KNLD + nb);
        }
#pragma unroll
        for (int im = 0; im < 4; im++)
#pragma unroll
            for (int jn = 0; jn < 4; jn++) mma_tf32(acc[im][jn], a[im], b[jn]);
    }
}

#define GEMM_SMEM (4 * GS * 4)   // 73728 B -> 2 blocks/SM

// ---------------------------------------------------------------------------
// K1a: direct left proj (qkv): t_y = rna(X @ L_y^T). grid (BT/128, 3).
// ---------------------------------------------------------------------------
__global__ __launch_bounds__(256, 2) void left_proj_direct(
    const float* __restrict__ X, const float* __restrict__ L, size_t Lstride,
    float* __restrict__ Tout, size_t Tstride) {
    extern __shared__ float gsm[];
    float* Aab = gsm;
    float* Bab = gsm + 2 * GS;
    int tid = threadIdx.x, lane = tid & 31, w = tid >> 5, wm = w >> 2, wn = w & 3;
    int m0 = blockIdx.x * 128;
    const float* Lp = L + blockIdx.y * Lstride;
    const float* Xp = X + (size_t)m0 * Cdim;
    float* Tp = Tout + blockIdx.y * Tstride;
    float acc[4][4][4] = {};

    cpa_128x32(Aab, Xp, Cdim, tid);
    cpa_128x32(Bab, Lp, Cdim, tid);
    CP_COMMIT();
    const int NS = Cdim / 32;
    for (int s = 0; s < NS; s++) {
        int st = s & 1;
        CP_WAIT0();
        __syncthreads();
        if (s + 1 < NS) {
            int nt = st ^ 1;
            cpa_128x32(Aab + nt * GS, Xp + (s + 1) * 32, Cdim, tid);
            cpa_128x32(Bab + nt * GS, Lp + (s + 1) * 32, Cdim, tid);
            CP_COMMIT();
        }
        mma_step_nk(Aab + st * GS, Bab + st * GS, wm, wn, lane, acc);
        __syncthreads();
    }
    int g = lane >> 2, tg = lane & 3;
#pragma unroll
    for (int im = 0; im < 4; im++)
#pragma unroll
        for (int jn = 0; jn < 4; jn++) {
            int r = m0 + wm * 64 + im * 16 + g;
            int c = wn * 32 + jn * 8 + tg * 2;
            Tp[(size_t)r * Rr + c]           = rnd(acc[im][jn][0]);
            Tp[(size_t)r * Rr + c + 1]       = rnd(acc[im][jn][1]);
            Tp[(size_t)(r + 8) * Rr + c]     = rnd(acc[im][jn][2]);
            Tp[(size_t)(r + 8) * Rr + c + 1] = rnd(acc[im][jn][3]);
        }
}

// ---------------------------------------------------------------------------
// K1b: split-K left proj (final): tpart[z] = Y @ L3^T over K chunk z.
// grid (BT/128, 1, KSPLIT).
// ---------------------------------------------------------------------------
__global__ __launch_bounds__(256, 2) void left_proj_split(
    const float* __restrict__ X, const float* __restrict__ L,
    float* __restrict__ Tpart) {
    extern __shared__ float gsm[];
    float* Aab = gsm;
    float* Bab = gsm + 2 * GS;
    int tid = threadIdx.x, lane = tid & 31, w = tid >> 5, wm = w >> 2, wn = w & 3;
    int m0 = blockIdx.x * 128;
    int kz = blockIdx.z * (Cdim / KSPLIT);
    const float* Lp = L + kz;
    const float* Xp = X + (size_t)m0 * Cdim + kz;
    float* Tp = Tpart + (size_t)blockIdx.z * ((size_t)BT * Rr);
    float acc[4][4][4] = {};

    cpa_128x32(Aab, Xp, Cdim, tid);
    cpa_128x32(Bab, Lp, Cdim, tid);
    CP_COMMIT();
    const int NS = Cdim / KSPLIT / 32;  // 16
    for (int s = 0; s < NS; s++) {
        int st = s & 1;
        CP_WAIT0();
        __syncthreads();
        if (s + 1 < NS) {
            int nt = st ^ 1;
            cpa_128x32(Aab + nt * GS, Xp + (s + 1) * 32, Cdim, tid);
            cpa_128x32(Bab + nt * GS, Lp + (s + 1) * 32, Cdim, tid);
            CP_COMMIT();
        }
        mma_step_nk(Aab + st * GS, Bab + st * GS, wm, wn, lane, acc);
        __syncthreads();
    }
    int g = lane >> 2, tg = lane & 3;
#pragma unroll
    for (int im = 0; im < 4; im++)
#pragma unroll
        for (int jn = 0; jn < 4; jn++) {
            int r = m0 + wm * 64 + im * 16 + g;
            int c = wn * 32 + jn * 8 + tg * 2;
            Tp[(size_t)r * Rr + c]           = acc[im][jn][0];
            Tp[(size_t)r * Rr + c + 1]       = acc[im][jn][1];
            Tp[(size_t)(r + 8) * Rr + c]     = acc[im][jn][2];
            Tp[(size_t)(r + 8) * Rr + c + 1] = acc[im][jn][3];
        }
}

// ---------------------------------------------------------------------------
// K2: fused LORI output, 128x128 tile (round-13 measured config).
// grid (BT/128, NB, nProj); z strides select layer.
// ---------------------------------------------------------------------------
__global__ __launch_bounds__(256, 2) void fused_out_mma(
    const float* __restrict__ X,
    const float* __restrict__ Tl, size_t Tstride,
    const float* __restrict__ Dg, size_t Dstride,
    const float* __restrict__ RW, size_t RWstride,
    const float* __restrict__ rb,
    const float* __restrict__ bp, size_t Bstride,
    float* __restrict__ Y, size_t Ystride, int round_out) {
    extern __shared__ float gsm[];
    float* Aab = gsm;
    float* Bab = gsm + 2 * GS;
    int tid = threadIdx.x, lane = tid & 31, w = tid >> 5, wm = w >> 2, wn = w & 3;
    int m0 = blockIdx.x * 128;
    int c0 = blockIdx.y * BS;
    int z = blockIdx.z;
    const float* Tlp = Tl + z * Tstride;
    const float* D   = Dg + z * Dstride + (size_t)blockIdx.y * BS * BS;
    const float* RWp = RW + z * RWstride;
    const float* rbp = rb + z * Bstride;
    const float* bpp = bp + z * Bstride;
    float* Yp        = Y  + z * Ystride;
    float acc[4][4][4] = {};

    // 8 steps: 0..3 blockdiag (B kn), 4..7 low-rank (B nk)
    cpa_128x32(Aab, X + (size_t)m0 * Cdim + c0, Cdim, tid);
    cpa_32x128(Bab, D, BS, tid);
    CP_COMMIT();
    for (int s = 0; s < 8; s++) {
        int st = s & 1;
        CP_WAIT0();
        __syncthreads();
        if (s + 1 < 8) {
            int nt = st ^ 1, s1 = s + 1;
            if (s1 < 4) {
                cpa_128x32(Aab + nt * GS, X + (size_t)m0 * Cdim + c0 + s1 * 32, Cdim, tid);
                cpa_32x128(Bab + nt * GS, D + (size_t)(s1 * 32) * BS, BS, tid);
            } else {
                cpa_128x32(Aab + nt * GS, Tlp + (size_t)m0 * Rr + (s1 - 4) * 32, Rr, tid);
                cpa_128x32(Bab + nt * GS, RWp + (size_t)c0 * Rr + (s1 - 4) * 32, Rr, tid);
            }
            CP_COMMIT();
        }
        if (s < 4) mma_step_kn(Aab + st * GS, Bab + st * GS, wm, wn, lane, acc);
        else       mma_step_nk(Aab + st * GS, Bab + st * GS, wm, wn, lane, acc);
        __syncthreads();
    }

    int g = lane >> 2, tg = lane & 3;
#pragma unroll
    for (int im = 0; im < 4; im++)
#pragma unroll
        for (int jn = 0; jn < 4; jn++) {
            int r = m0 + wm * 64 + im * 16 + g;
            int c = c0 + wn * 32 + jn * 8 + tg * 2;
            float b0 = rbp[c] + bpp[c], b1 = rbp[c + 1] + bpp[c + 1];
            float o00 = acc[im][jn][0] + b0, o01 = acc[im][jn][1] + b1;
            float o10 = acc[im][jn][2] + b0, o11 = acc[im][jn][3] + b1;
            if (round_out) { o00 = rnd(o00); o01 = rnd(o01); o10 = rnd(o10); o11 = rnd(o11); }
            Yp[(size_t)r * Cdim + c]           = o00;
            Yp[(size_t)r * Cdim + c + 1]       = o01;
            Yp[(size_t)(r + 8) * Cdim + c]     = o10;
            Yp[(size_t)(r + 8) * Cdim + c + 1] = o11;
        }
}

// ---------------------------------------------------------------------------
// K3: fused flash attention. grid (qt=16, bh=64), 8 warps. Q/K/V tf32-exact.
// ---------------------------------------------------------------------------
#define QLD 132
#define KLD 132
#define VLD 136
#define FA_SMEM ((128 * QLD + 128 * KLD + 128 * VLD) * 4)

__global__ __launch_bounds__(256) void flash_attn(const float* __restrict__ Q,
                                                  const float* __restrict__ Kg,
                                                  const float* __restrict__ Vg,
                                                  float* __restrict__ Y) {
    extern __shared__ float fsm[];
    float* Qs = fsm;
    float* Ks = fsm + 128 * QLD;
    float* Vs = fsm + 128 * QLD + 128 * KLD;

    int qt = gridDim.x - 1 - blockIdx.x;
    int bh = blockIdx.y;
    int b = bh / H, h = bh % H;
    const float* Qp = Q  + (size_t)b * Tdim * Cdim + (size_t)h * HD;
    const float* Kp = Kg + (size_t)b * Tdim * Cdim + (size_t)h * HD;
    const float* Vp = Vg + (size_t)b * Tdim * Cdim + (size_t)h * HD;
    float* Yp       = Y  + (size_t)b * Tdim * Cdim + (size_t)h * HD;

    int tid = threadIdx.x, lane = tid & 31, w = tid >> 5;
    int g = lane >> 2, tg = lane & 3;
    int qr = w * 16;

#pragma unroll
    for (int p = 0; p < 16; p++) {
        int idx = tid + p * 256;
        int row = idx >> 5, c4 = (idx & 31) << 2;
        cp_async16(Qs + row * QLD + c4, Qp + (size_t)(qt * 128 + row) * Cdim + c4);
    }
#pragma unroll
    for (int p = 0; p < 16; p++) {
        int idx = tid + p * 256;
        int row = idx >> 5, c4 = (idx & 31) << 2;
        cp_async16(Ks + row * KLD + c4, Kp + (size_t)row * Cdim + c4);
    }
    CP_COMMIT();
#pragma unroll
    for (int p = 0; p < 16; p++) {
        int idx = tid + p * 256;
        int row = idx >> 5, c4 = (idx & 31) << 2;
        cp_async16(Vs + row * VLD + c4, Vp + (size_t)row * Cdim + c4);
    }
    CP_COMMIT();

    float acco[16][4] = {};
    float m0 = -1e30f, m1 = -1e30f;
    float l0 = 0.f, l1 = 0.f;

    for (int kt = 0; kt <= qt; kt++) {
        CP_WAIT1();
        __syncthreads();

        float accs[16][4] = {};
#pragma unroll
        for (int kk = 0; kk < 16; kk++) {
            int kg = kk * 8;
            unsigned aq[4];
            const float* q0 = Qs + (qr + g) * QLD;
            aq[0] = ldu(q0 + kg + tg);
            aq[1] = ldu(q0 + 8 * QLD + kg + tg);
            aq[2] = ldu(q0 + kg + tg + 4);
            aq[3] = ldu(q0 + 8 * QLD + kg + tg + 4);
#pragma unroll
            for (int nb = 0; nb < 16; nb++) {
                unsigned bb[2];
                const float* kr = Ks + (nb * 8 + g) * KLD;
                bb[0] = ldu(kr + kg + tg);
                bb[1] = ldu(kr + kg + tg + 4);
                mma_tf32(accs[nb], aq, bb);
            }
        }
        __syncthreads();
        if (kt < qt) {
#pragma unroll
            for (int p = 0; p < 16; p++) {
                int idx = tid + p * 256;
                int row = idx >> 5, c4 = (idx & 31) << 2;
                cp_async16(Ks + row * KLD + c4,
                           Kp + (size_t)((kt + 1) * 128 + row) * Cdim + c4);
            }
            CP_COMMIT();
        }

        bool diag = (kt == qt);
        int rl0 = qr + g, rl1 = qr + g + 8;
        float mx0 = -1e30f, mx1 = -1e30f;
#pragma unroll
        for (int nb = 0; nb < 16; nb++) {
            int cl = nb * 8 + 2 * tg;
            float v0 = accs[nb][0] * SCALE_ATT;
            float v1 = accs[nb][1] * SCALE_ATT;
            float v2 = accs[nb][2] * SCALE_ATT;
            float v3 = accs[nb][3] * SCALE_ATT;
            if (diag) {
                if (cl     > rl0) v0 = -1e30f;
                if (cl + 1 > rl0) v1 = -1e30f;
                if (cl     > rl1) v2 = -1e30f;
                if (cl + 1 > rl1) v3 = -1e30f;
            }
            accs[nb][0] = v0; accs[nb][1] = v1; accs[nb][2] = v2; accs[nb][3] = v3;
            mx0 = fmaxf(mx0, fmaxf(v0, v1));
            mx1 = fmaxf(mx1, fmaxf(v2, v3));
        }
        mx0 = fmaxf(mx0, __shfl_xor_sync(FULLM, mx0, 1));
        mx0 = fmaxf(mx0, __shfl_xor_sync(FULLM, mx0, 2));
        mx1 = fmaxf(mx1, __shfl_xor_sync(FULLM, mx1, 1));
        mx1 = fmaxf(mx1, __shfl_xor_sync(FULLM, mx1, 2));

        float mn0 = fmaxf(m0, mx0), mn1 = fmaxf(m1, mx1);
        float sc0 = __expf(m0 - mn0), sc1 = __expf(m1 - mn1);
        m0 = mn0; m1 = mn1;
        float s0 = 0.f, s1 = 0.f;
#pragma unroll
        for (int nb = 0; nb < 16; nb++) {
            float p0 = __expf(accs[nb][0] - mn0);
            float p1 = __expf(accs[nb][1] - mn0);
            float p2 = __expf(accs[nb][2] - mn1);
            float p3 = __expf(accs[nb][3] - mn1);
            s0 += p0 + p1; s1 += p2 + p3;
            accs[nb][0] = __uint_as_float(f2tf32(p0));
            accs[nb][1] = __uint_as_float(f2tf32(p1));
            accs[nb][2] = __uint_as_float(f2tf32(p2));
            accs[nb][3] = __uint_as_float(f2tf32(p3));
        }
        s0 += __shfl_xor_sync(FULLM, s0, 1);
        s0 += __shfl_xor_sync(FULLM, s0, 2);
        s1 += __shfl_xor_sync(FULLM, s1, 1);
        s1 += __shfl_xor_sync(FULLM, s1, 2);
        l0 = l0 * sc0 + s0; l1 = l1 * sc1 + s1;
#pragma unroll
        for (int nb = 0; nb < 16; nb++) {
            acco[nb][0] *= sc0; acco[nb][1] *= sc0;
            acco[nb][2] *= sc1; acco[nb][3] *= sc1;
        }

        if (kt < qt) CP_WAIT1(); else CP_WAIT0();   // last-iter edge case
        __syncthreads();

#pragma unroll
        for (int kb = 0; kb < 16; kb++) {
            float c0 = accs[kb][0], c1 = accs[kb][1];
            float c2 = accs[kb][2], c3 = accs[kb][3];
            int q0 = (lane & ~3) | (tg >> 1);
            int q1 = q0 | 2;
            bool odd = tg & 1;
            float t00 = __shfl_sync(FULLM, c0, q0), t01 = __shfl_sync(FULLM, c1, q0);
            float t10 = __shfl_sync(FULLM, c2, q0), t11 = __shfl_sync(FULLM, c3, q0);
            float t20 = __shfl_sync(FULLM, c0, q1), t21 = __shfl_sync(FULLM, c1, q1);
            float t30 = __shfl_sync(FULLM, c2, q1), t31 = __shfl_sync(FULLM, c3, q1);
            unsigned ap[4];
            ap[0] = __float_as_uint(odd ? t01 : t00);
            ap[1] = __float_as_uint(odd ? t11 : t10);
            ap[2] = __float_as_uint(odd ? t21 : t20);
            ap[3] = __float_as_uint(odd ? t31 : t30);
            int kg = kb * 8;
#pragma unroll
            for (int nb = 0; nb < 16; nb++) {
                unsigned bb[2];
                bb[0] = ldu(Vs + (kg + tg) * VLD + nb * 8 + g);
                bb[1] = ldu(Vs + (kg + tg + 4) * VLD + nb * 8 + g);
                mma_tf32(acco[nb], ap, bb);
            }
        }
        __syncthreads();
        if (kt < qt) {
#pragma unroll
            for (int p = 0; p < 16; p++) {
                int idx = tid + p * 256;
                int row = idx >> 5, c4 = (idx & 31) << 2;
                cp_async16(Vs + row * VLD + c4,
                           Vp + (size_t)((kt + 1) * 128 + row) * Cdim + c4);
            }
            CP_COMMIT();
        }
    }

    float inv0 = 1.0f / l0, inv1 = 1.0f / l1;
    int r0 = qt * 128 + qr + g, r1 = r0 + 8;
#pragma unroll
    for (int nb = 0; nb < 16; nb++) {
        int cc = nb * 8 + 2 * tg;
        float2 o0 = make_float2(rnd(acco[nb][0] * inv0), rnd(acco[nb][1] * inv0));
        float2 o1 = make_float2(rnd(acco[nb][2] * inv1), rnd(acco[nb][3] * inv1));
        *(float2*)(Yp + (size_t)r0 * Cdim + cc) = o0;
        *(float2*)(Yp + (size_t)r1 * Cdim + cc) = o1;
    }
}

// ---------------------------------------------------------------------------
extern "C" void kernel_launch(void* const* d_in, const int* in_sizes, int n_in,
                              void* d_out, int out_size) {
    const float* x    = (const float*)d_in[0];
    const float* diag = (const float*)d_in[1];
    const float* left = (const float*)d_in[2];
    const float* rw   = (const float*)d_in[3];
    const float* rb   = (const float*)d_in[4];
    const float* bp   = (const float*)d_in[5];
    float* out = (float*)d_out;

    float *pxr, *pwr, *ptpart, *pt, *pqkv, *py;
    cudaGetSymbolAddress((void**)&pxr, g_xr);
    cudaGetSymbolAddress((void**)&pwr, g_wr);
    cudaGetSymbolAddress((void**)&ptpart, g_tpart);
    cudaGetSymbolAddress((void**)&pt, g_t);
    cudaGetSymbolAddress((void**)&pqkv, g_qkv);
    cudaGetSymbolAddress((void**)&py, g_y);

    static bool attr_done = false;
    if (!attr_done) {
        cudaFuncSetAttribute(flash_attn, cudaFuncAttributeMaxDynamicSharedMemorySize, FA_SMEM);
        cudaFuncSetAttribute(left_proj_direct, cudaFuncAttributeMaxDynamicSharedMemorySize, GEMM_SMEM);
        cudaFuncSetAttribute(left_proj_split, cudaFuncAttributeMaxDynamicSharedMemorySize, GEMM_SMEM);
        cudaFuncSetAttribute(fused_out_mma, cudaFuncAttributeMaxDynamicSharedMemorySize, GEMM_SMEM);
        attr_done = true;
    }

    const size_t PC = (size_t)BT * Cdim;   // activation plane
    const size_t PT = (size_t)BT * Rr;     // t plane
    float* plw = pwr;                      // rounded left_w
    float* prw = pwr + WSZ;                // rounded right_w
    float* pdg = pwr + 2 * WSZ;            // rounded diag

    // 0. pre-round x + weights (rna-tf32); inner loops stay cvt-free.
    round_x_kernel<<<1184, 256>>>(x, pxr, PC / 4);
    round_w_kernel<<<512, 256>>>(left, rw, diag, pwr);

    // 1. q,k,v left proj (direct, rounded epilogue)
    left_proj_direct<<<dim3(BT / 128, 3), 256, GEMM_SMEM>>>(
        pxr, plw, (size_t)Rr * Cdim, pt, PT);

    // 2. q,k,v fused output (rounded for flash)
    fused_out_mma<<<dim3(BT / 128, NB, 3), 256, GEMM_SMEM>>>(
        pxr, pt, PT,
        pdg, (size_t)NB * BS * BS,
        prw, (size_t)Cdim * Rr,
        rb, bp, (size_t)Cdim,
        pqkv, PC, 1);

    // 3. attention (y rounded in epilogue)
    flash_attn<<<dim3(16, NBH), 256, FA_SMEM>>>(pqkv, pqkv + PC, pqkv + 2 * PC, py);

    // 4. output projection: split-K left + reduce + fused
    left_proj_split<<<dim3(BT / 128, 1, KSPLIT), 256, GEMM_SMEM>>>(
        py, plw + (size_t)3 * Rr * Cdim, ptpart);
    reduce_t_kernel<<<1184, 256>>>(ptpart, pt, PT / 4, PT / 4);
    fused_out_mma<<<dim3(BT / 128, NB, 1), 256, GEMM_SMEM>>>(
        py, pt, 0,
        pdg + (size_t)3 * NB * BS * BS, 0,
        prw + (size_t)3 * Cdim * Rr, 0,
        rb + (size_t)3 * Cdim, bp + (size_t)3 * Cdim, 0,
        out, PC, 0);
}